// round 16
// baseline (speedup 1.0000x reference)
#include <cuda_runtime.h>
#include <cuda_fp16.h>
#include <cstdint>

#define HH 64
#define WW 64
#define NPIX 4096
#define NB 4
#define C1 32
#define C2 64
#define C3 256

typedef unsigned long long ull;

__device__ __forceinline__ uint32_t smem_u32(const void* p) {
    uint32_t a;
    asm("{ .reg .u64 t; cvta.to.shared.u64 t, %1; cvt.u32.u64 %0, t; }" : "=r"(a) : "l"(p));
    return a;
}
#define CP_ASYNC16(dst, src) \
    asm volatile("cp.async.cg.shared.global [%0], [%1], 16;" :: "r"(dst), "l"(src) : "memory")
#define CP_COMMIT() asm volatile("cp.async.commit_group;" ::: "memory")
#define CP_WAIT1() asm volatile("cp.async.wait_group 1;" ::: "memory")
#define CP_WAIT0() asm volatile("cp.async.wait_group 0;" ::: "memory")
#define LDSM_X4(r0, r1, r2, r3, a) \
    asm volatile("ldmatrix.sync.aligned.m8n8.x4.shared.b16 {%0,%1,%2,%3}, [%4];" \
        : "=r"(r0), "=r"(r1), "=r"(r2), "=r"(r3) : "r"(a))
#define LDSM_X2(r0, r1, a) \
    asm volatile("ldmatrix.sync.aligned.m8n8.x2.shared.b16 {%0,%1}, [%2];" \
        : "=r"(r0), "=r"(r1) : "r"(a))
#define LDSM_X2T(r0, r1, a) \
    asm volatile("ldmatrix.sync.aligned.m8n8.x2.trans.shared.b16 {%0,%1}, [%2];" \
        : "=r"(r0), "=r"(r1) : "r"(a))
#define MMA_F16(d, a, bf) \
    asm volatile( \
        "mma.sync.aligned.m16n8k16.row.col.f32.f16.f16.f32 " \
        "{%0,%1,%2,%3}, {%4,%5,%6,%7}, {%8,%9}, {%0,%1,%2,%3};" \
        : "+f"((d)[0]), "+f"((d)[1]), "+f"((d)[2]), "+f"((d)[3]) \
        : "r"((a)[0]), "r"((a)[1]), "r"((a)[2]), "r"((a)[3]), "r"((bf)[0]), "r"((bf)[1]))

__device__ __forceinline__ uint32_t fkey(float f) {
    uint32_t b = __float_as_uint(f);
    return (b & 0x80000000u) ? ~b : (b | 0x80000000u);
}

// ---------------- static device scratch ----------------
__device__ float g_T1[2 * NB * C1 * NPIX];
__device__ float g_T2[2 * NB * C2 * NPIX];
__device__ __align__(16) __half g_ICh[(long)2 * NB * 576 * NPIX];
__device__ __align__(16) __half g_ICm[(long)2 * NB * 576 * NPIX];
__device__ float g_F2[NB * C3 * NPIX];
__device__ float g_B2N[NB * NPIX];
__device__ ull g_AMIN[NB * NPIX];
__device__ __align__(16) __half g_Wh2[C2 * 288];
__device__ __align__(16) __half g_Wm2[C2 * 288];
__device__ __align__(16) __half g_Wh3[C3 * 576];
__device__ __align__(16) __half g_Wm3[C3 * 576];
__device__ __align__(16) __half g_QS[(long)NB * NPIX * 512];
__device__ __align__(16) __half g_KS[(long)NB * NPIX * 512];

// ---------------- prep: split weights to fp16 h/m ----------------
__global__ void prep_kernel(const float* __restrict__ w2, const float* __restrict__ w3,
                            __half* __restrict__ Wh2, __half* __restrict__ Wm2,
                            __half* __restrict__ Wh3, __half* __restrict__ Wm3) {
    int t = blockIdx.x * blockDim.x + threadIdx.x;
    if (t < C2 * 288) {
        float x = w2[t];
        __half h = __float2half_rn(x);
        Wh2[t] = h;
        Wm2[t] = __float2half_rn(x - __half2float(h));
    } else {
        int u = t - C2 * 288;
        if (u < C3 * 576) {
            float x = w3[u];
            __half h = __float2half_rn(x);
            Wh3[u] = h;
            Wm3[u] = __float2half_rn(x - __half2float(h));
        }
    }
}

// ---------------- conv1 (fp32 direct) ----------------
__global__ void conv1_kernel(const float* __restrict__ x1, const float* __restrict__ x2,
                             const float* __restrict__ w, const float* __restrict__ bias,
                             float* __restrict__ out) {
    int p = blockIdx.x * blockDim.x + threadIdx.x;
    int z = blockIdx.y;
    if (p >= NPIX) return;
    const float* x = (z >> 2) ? x2 : x1;
    int b = z & 3;
    int y = p >> 6, xx = p & 63;
    const float* xb = x + (long)b * NPIX;
    float in[9];
#pragma unroll
    for (int ky = 0; ky < 3; ky++)
#pragma unroll
        for (int kx = 0; kx < 3; kx++) {
            int yy = y + ky - 1, xc = xx + kx - 1;
            in[ky * 3 + kx] =
                ((unsigned)yy < (unsigned)HH && (unsigned)xc < (unsigned)WW) ? xb[yy * WW + xc] : 0.f;
        }
#pragma unroll 4
    for (int co = 0; co < C1; co++) {
        float acc = bias[co];
#pragma unroll
        for (int t = 0; t < 9; t++) acc += w[co * 9 + t] * in[t];
        out[((long)z * C1 + co) * NPIX + p] = acc;
    }
}

// ---------------- im2col with fp16 h/m split ----------------
__global__ void im2col_kernel(const float* __restrict__ in, int CI,
                              __half* __restrict__ oh, __half* __restrict__ om) {
    int gk = blockIdx.x;
    int z = blockIdx.y;
    int n = ((blockIdx.z << 8) + threadIdx.x) << 1;
    int K = CI * 9;
    int ci = gk / 9;
    int tap = gk - ci * 9;
    int ky = tap / 3 - 1, kx = tap - (tap / 3) * 3 - 1;
    int y = (n >> 6) + ky;
    int x = (n & 63) + kx;
    const float* row = in + ((long)(z * CI + ci) << 12) + (y << 6);
    float v0 = 0.f, v1 = 0.f;
    if ((unsigned)y < 64u) {
        if ((unsigned)x < 64u) v0 = row[x];
        if ((unsigned)(x + 1) < 64u) v1 = row[x + 1];
    }
    __half h0 = __float2half_rn(v0), h1 = __float2half_rn(v1);
    long o = ((long)(z * K + gk) << 12) + n;
    *(__half2*)&oh[o] = __halves2half2(h0, h1);
    *(__half2*)&om[o] = __halves2half2(__float2half_rn(v0 - __half2float(h0)),
                                       __float2half_rn(v1 - __half2float(h1)));
}

// ---------------- conv via mma.sync fp16 3-product (round-15 proven) ----------------
template <int MROWS>
__global__ void __launch_bounds__(256, 2)
conv_mma_kernel(const __half* __restrict__ Wh, const __half* __restrict__ Wm,
                const __half* __restrict__ Bh, const __half* __restrict__ Bm, int K,
                const float* __restrict__ bias,
                float* __restrict__ outA, long sA, float* __restrict__ outB, long sB) {
    extern __shared__ __align__(16) char csm[];
    const int AG = MROWS * 4;
    const int STB = (2 * AG + 1024) * 16;
    const int ABYT = 2 * AG * 16;
    const int TMT = MROWS / 32;
    uint32_t sb = smem_u32(csm);
    int z = blockIdx.z, sel = z >> 2, bb = z & 3;
    float* out = sel ? outB : outA;
    long os = sel ? sB : sA;
    int m0 = blockIdx.y * MROWS;
    int n0 = blockIdx.x * 128;
    int tid = threadIdx.x;
    int lane = tid & 31, wid = tid >> 5;
    int wm = wid & 1, wn = wid >> 1;
    long zK = (long)z * K;

    float acc[TMT][4][4];
#pragma unroll
    for (int mt = 0; mt < TMT; mt++)
#pragma unroll
        for (int nt = 0; nt < 4; nt++)
#pragma unroll
            for (int q = 0; q < 4; q++) acc[mt][nt][q] = 0.f;

    auto issue = [&](int c, int st) {
        int kb = c * 32;
        uint32_t da = sb + (uint32_t)st * STB;
        uint32_t db = da + ABYT;
#pragma unroll
        for (int it = 0; it < 2 * AG / 256; it++) {
            int e = tid + it * 256;
            int seg = e / AG;
            int r = (e % AG) >> 2;
            int k8 = e & 3;
            uint32_t g = (uint32_t)(seg * AG + r * 4 + (k8 ^ ((r >> 1) & 3))) << 4;
            const __half* src = (seg ? Wm : Wh) + (long)(m0 + r) * K + kb + k8 * 8;
            CP_ASYNC16(da + g, src);
        }
#pragma unroll
        for (int it = 0; it < 4; it++) {
            int e = tid + it * 256;
            int seg = e >> 9;
            int k = (e >> 4) & 31;
            int ng = e & 15;
            uint32_t g = (uint32_t)(seg * 512 + k * 16 + (ng ^ (k & 15))) << 4;
            const __half* src = (seg ? Bm : Bh) + ((zK + kb + k) << 12) + n0 + ng * 8;
            CP_ASYNC16(db + g, src);
        }
        CP_COMMIT();
    };

    int NCH = K / 32;
    issue(0, 0);
    issue(1, 1);

    for (int c = 0; c < NCH; c++) {
        int st = c % 3;
        if (c + 1 < NCH) CP_WAIT1(); else CP_WAIT0();
        __syncthreads();
        if (c + 2 < NCH) issue(c + 2, (c + 2) % 3);
        uint32_t Ab = sb + (uint32_t)st * STB;
        uint32_t Bb = Ab + ABYT;
#pragma unroll
        for (int ks = 0; ks < 2; ks++) {
            uint32_t bf[2][4][2];
#pragma unroll
            for (int sk = 0; sk < 2; sk++)
#pragma unroll
                for (int nt = 0; nt < 4; nt++) {
                    int k = ks * 16 + (lane & 15);
                    int ng = wn * 4 + nt;
                    uint32_t g = (uint32_t)(sk * 512 + k * 16 + (ng ^ (k & 15))) << 4;
                    LDSM_X2T(bf[sk][nt][0], bf[sk][nt][1], Bb + g);
                }
#pragma unroll
            for (int sq = 0; sq < 2; sq++) {
                uint32_t af[TMT][4];
#pragma unroll
                for (int mt = 0; mt < TMT; mt++) {
                    int row = wm * (MROWS / 2) + mt * 16 + (lane & 15);
                    int k8 = ks * 2 + (lane >> 4);
                    uint32_t g = (uint32_t)(sq * AG + row * 4 + (k8 ^ ((row >> 1) & 3))) << 4;
                    LDSM_X4(af[mt][0], af[mt][1], af[mt][2], af[mt][3], Ab + g);
                }
                int nsk = 2 - sq;
#pragma unroll
                for (int sk = 0; sk < 2; sk++) {
                    if (sk >= nsk) break;
#pragma unroll
                    for (int mt = 0; mt < TMT; mt++)
#pragma unroll
                        for (int nt = 0; nt < 4; nt++) MMA_F16(acc[mt][nt], af[mt], bf[sk][nt]);
                }
            }
        }
    }
#pragma unroll
    for (int mt = 0; mt < TMT; mt++) {
        int co0 = m0 + wm * (MROWS / 2) + mt * 16 + (lane >> 2);
        int co1 = co0 + 8;
        float b0 = bias[co0], b1 = bias[co1];
        long base0 = (long)bb * os + ((long)co0 << 12) + n0;
        long base1 = (long)bb * os + ((long)co1 << 12) + n0;
#pragma unroll
        for (int nt = 0; nt < 4; nt++) {
            int nn = wn * 32 + nt * 8 + (lane & 3) * 2;
            float2 o0, o1;
            o0.x = acc[mt][nt][0] + b0;
            o0.y = acc[mt][nt][1] + b0;
            o1.x = acc[mt][nt][2] + b1;
            o1.y = acc[mt][nt][3] + b1;
            *(float2*)&out[base0 + nn] = o0;
            *(float2*)&out[base1 + nn] = o1;
        }
    }
}

// ---------------- split to fp16 h/m stacks + key norms + AMIN init ----------------
__global__ void split_kernel(const float* __restrict__ f1out, const float* __restrict__ f2,
                             __half* __restrict__ QS, __half* __restrict__ KS,
                             float* __restrict__ b2n, ull* __restrict__ amin) {
    __shared__ __half sh[2][64][64];
    __shared__ float snorm[256];
    int n0 = blockIdx.x * 64;
    int src = blockIdx.y;
    int b = blockIdx.z;
    const float* f = src ? (f2 + (long)b * C3 * NPIX) : (f1out + (long)b * 512 * NPIX);
    __half* dst = (src ? KS : QS) + (long)b * NPIX * 512;
    int tid = threadIdx.x;
    int nl = tid & 63, cq = tid >> 6;
    if (src == 0 && tid < 64) amin[b * NPIX + n0 + tid] = ~0ull;
    float nacc = 0.f;
    for (int cc = 0; cc < 4; cc++) {
        int cbase = cc * 64;
#pragma unroll
        for (int r = 0; r < 16; r++) {
            int cl = cq + r * 4;
            float x = f[(long)(cbase + cl) * NPIX + n0 + nl];
            __half h = __float2half_rn(x);
            sh[0][cl][nl] = h;
            sh[1][cl][nl] = __float2half_rn(x - __half2float(h));
            nacc += x * x;
        }
        __syncthreads();
        int nl2 = tid >> 2;
        int cg = (tid & 3) * 16;
#pragma unroll
        for (int s = 0; s < 2; s++) {
            __half* drow = dst + (long)(n0 + nl2) * 512 + s * 256 + cbase + cg;
#pragma unroll
            for (int j = 0; j < 16; j++) drow[j] = sh[s][cg + j][nl2];
        }
        __syncthreads();
    }
    if (src == 1) {
        snorm[tid] = nacc;
        __syncthreads();
        if (tid < 64)
            b2n[(long)b * NPIX + n0 + tid] =
                snorm[tid] + snorm[tid + 64] + snorm[tid + 128] + snorm[tid + 192];
    }
}

// ---------------- dist GEMM + argmin: 128i x 256j, fp16 3-product, atomicMin merge ----------------
#define MST 49152
#define MSM_TOTAL (2 * MST)

__global__ void __launch_bounds__(512, 1)
dist_mma_kernel(const __half* __restrict__ QS, const __half* __restrict__ KS,
                const float* __restrict__ b2n, ull* __restrict__ amin) {
    extern __shared__ __align__(16) char dsm[];
    uint32_t sb = smem_u32(dsm);
    int b = blockIdx.z;
    int jq = blockIdx.y;
    int j0 = jq * 256;
    int i0 = blockIdx.x * 128;
    int tid = threadIdx.x;
    int lane = tid & 31, wid = tid >> 5;
    int wm = wid & 1, wn = wid >> 1;  // 2 x 8 warps

    const __half* Qb = QS + (long)(b * NPIX + i0) * 512;
    const __half* Kb = KS + (long)(b * NPIX + j0) * 512;
    const float* bn = b2n + (long)b * NPIX;

    float acc[4][4][4];
#pragma unroll
    for (int mt = 0; mt < 4; mt++)
#pragma unroll
        for (int nt = 0; nt < 4; nt++)
#pragma unroll
            for (int q = 0; q < 4; q++) acc[mt][nt][q] = 0.f;

    // stage: Q 2segs x 128rows x 4 k8 (16KB) + K 2 x 256 x 4 (32KB)
    auto issue = [&](int c, int st) {
        uint32_t dq = sb + (uint32_t)st * MST;
        uint32_t dk = dq + 16384;
        int kb = c * 32;
#pragma unroll
        for (int it = 0; it < 2; it++) {
            int e = tid + it * 512;
            int s = e >> 9;
            int row = (e >> 2) & 127;
            int k8 = e & 3;
            uint32_t g = (uint32_t)((s << 9) + row * 4 + (k8 ^ ((row >> 1) & 3))) << 4;
            CP_ASYNC16(dq + g, Qb + (long)row * 512 + s * 256 + kb + k8 * 8);
        }
#pragma unroll
        for (int it = 0; it < 4; it++) {
            int e = tid + it * 512;
            int s = e >> 10;
            int row = (e >> 2) & 255;
            int k8 = e & 3;
            uint32_t g = (uint32_t)((s << 10) + row * 4 + (k8 ^ ((row >> 1) & 3))) << 4;
            CP_ASYNC16(dk + g, Kb + (long)row * 512 + s * 256 + kb + k8 * 8);
        }
        CP_COMMIT();
    };

    const int NCH = 8;
    issue(0, 0);

    for (int c = 0; c < NCH; c++) {
        int st = c & 1;
        CP_WAIT0();
        __syncthreads();
        if (c + 1 < NCH) issue(c + 1, 1 - st);
        uint32_t Ab = sb + (uint32_t)st * MST;
        uint32_t Bb = Ab + 16384;
#pragma unroll
        for (int ks = 0; ks < 2; ks++) {
            uint32_t bf[2][4][2];
#pragma unroll
            for (int sk = 0; sk < 2; sk++)
#pragma unroll
                for (int nt = 0; nt < 4; nt++) {
                    int rowb = wn * 32 + nt * 8 + (lane & 7);
                    int k8 = ks * 2 + ((lane >> 3) & 1);
                    uint32_t g = (uint32_t)((sk << 10) + rowb * 4 + (k8 ^ ((rowb >> 1) & 3))) << 4;
                    LDSM_X2(bf[sk][nt][0], bf[sk][nt][1], Bb + g);
                }
#pragma unroll
            for (int sq = 0; sq < 2; sq++) {
                uint32_t af[4][4];
#pragma unroll
                for (int mt = 0; mt < 4; mt++) {
                    int row = wm * 64 + mt * 16 + (lane & 15);
                    int k8 = ks * 2 + (lane >> 4);
                    uint32_t g = (uint32_t)((sq << 9) + row * 4 + (k8 ^ ((row >> 1) & 3))) << 4;
                    LDSM_X4(af[mt][0], af[mt][1], af[mt][2], af[mt][3], Ab + g);
                }
                int nsk = 2 - sq;
#pragma unroll
                for (int sk = 0; sk < 2; sk++) {
                    if (sk >= nsk) break;
#pragma unroll
                    for (int mt = 0; mt < 4; mt++)
#pragma unroll
                        for (int nt = 0; nt < 4; nt++) MMA_F16(acc[mt][nt], af[mt], bf[sk][nt]);
                }
            }
        }
    }

    // epilogue: dist = bn[j] - 2*cross, running argmin (first-index ties)
    float bnv[4][2];
#pragma unroll
    for (int nt = 0; nt < 4; nt++) {
        int jj = j0 + wn * 32 + nt * 8 + (lane & 3) * 2;
        bnv[nt][0] = __ldg(&bn[jj]);
        bnv[nt][1] = __ldg(&bn[jj + 1]);
    }
    float bvA[4], bvB[4];
    int biA[4], biB[4];
#pragma unroll
    for (int mt = 0; mt < 4; mt++) {
        bvA[mt] = 3.4e38f; biA[mt] = 0;
        bvB[mt] = 3.4e38f; biB[mt] = 0;
#pragma unroll
        for (int nt = 0; nt < 4; nt++)
#pragma unroll
            for (int p = 0; p < 2; p++) {
                int j = j0 + wn * 32 + nt * 8 + (lane & 3) * 2 + p;
                float dA = bnv[nt][p] - 2.f * acc[mt][nt][p];
                if (dA < bvA[mt]) { bvA[mt] = dA; biA[mt] = j; }
                float dB = bnv[nt][p] - 2.f * acc[mt][nt][2 + p];
                if (dB < bvB[mt]) { bvB[mt] = dB; biB[mt] = j; }
            }
#pragma unroll
        for (int m = 1; m <= 2; m <<= 1) {
            float ov = __shfl_xor_sync(0xffffffffu, bvA[mt], m);
            int oi = __shfl_xor_sync(0xffffffffu, biA[mt], m);
            if (ov < bvA[mt] || (ov == bvA[mt] && oi < biA[mt])) { bvA[mt] = ov; biA[mt] = oi; }
            ov = __shfl_xor_sync(0xffffffffu, bvB[mt], m);
            oi = __shfl_xor_sync(0xffffffffu, biB[mt], m);
            if (ov < bvB[mt] || (ov == bvB[mt] && oi < biB[mt])) { bvB[mt] = ov; biB[mt] = oi; }
        }
    }
    __syncthreads();
    float* rv = (float*)dsm;               // [8 wn][128 rows]
    int* ri = (int*)(dsm + 4096);
    if ((lane & 3) == 0) {
#pragma unroll
        for (int mt = 0; mt < 4; mt++) {
            int r = wm * 64 + mt * 16 + (lane >> 2);
            rv[wn * 128 + r] = bvA[mt];
            ri[wn * 128 + r] = biA[mt];
            rv[wn * 128 + r + 8] = bvB[mt];
            ri[wn * 128 + r + 8] = biB[mt];
        }
    }
    __syncthreads();
    if (tid < 128) {
        float bv = rv[tid];
        int bi = ri[tid];
#pragma unroll
        for (int w = 1; w < 8; w++) {
            float v = rv[w * 128 + tid];
            int ii = ri[w * 128 + tid];
            if (v < bv || (v == bv && ii < bi)) { bv = v; bi = ii; }
        }
        ull key = ((ull)fkey(bv) << 32) | (uint32_t)bi;
        atomicMin(&amin[b * NPIX + i0 + tid], key);
    }
}

// ---------------- gather (reads atomic argmin result) ----------------
__global__ void gather_kernel(const float* __restrict__ f2, const ull* __restrict__ amin,
                              float* __restrict__ out) {
    long t = (long)blockIdx.x * blockDim.x + threadIdx.x;
    if (t >= (long)NB * C3 * NPIX) return;
    int j = (int)(t & (NPIX - 1));
    int c = (int)((t >> 12) & 255);
    int b = (int)(t >> 20);
    int id = (int)(amin[b * NPIX + j] & 0xFFFFFFFFull);
    out[((long)b * 512 + 256 + c) * NPIX + j] = f2[((long)b * C3 + c) * NPIX + id];
}

// ---------------- launch ----------------
extern "C" void kernel_launch(void* const* d_in, const int* in_sizes, int n_in,
                              void* d_out, int out_size) {
    const float* x1 = (const float*)d_in[0];
    const float* x2 = (const float*)d_in[1];
    const float* w1 = (const float*)d_in[2];
    const float* b1 = (const float*)d_in[3];
    const float* w2 = (const float*)d_in[4];
    const float* b2 = (const float*)d_in[5];
    const float* w3 = (const float*)d_in[6];
    const float* b3 = (const float*)d_in[7];
    float* out = (float*)d_out;

    float *T1, *T2, *F2, *B2N;
    ull* AMIN;
    __half *ICh, *ICm, *Wh2, *Wm2, *Wh3, *Wm3, *QS, *KS;
    cudaGetSymbolAddress((void**)&T1, g_T1);
    cudaGetSymbolAddress((void**)&T2, g_T2);
    cudaGetSymbolAddress((void**)&ICh, g_ICh);
    cudaGetSymbolAddress((void**)&ICm, g_ICm);
    cudaGetSymbolAddress((void**)&F2, g_F2);
    cudaGetSymbolAddress((void**)&B2N, g_B2N);
    cudaGetSymbolAddress((void**)&AMIN, g_AMIN);
    cudaGetSymbolAddress((void**)&Wh2, g_Wh2);
    cudaGetSymbolAddress((void**)&Wm2, g_Wm2);
    cudaGetSymbolAddress((void**)&Wh3, g_Wh3);
    cudaGetSymbolAddress((void**)&Wm3, g_Wm3);
    cudaGetSymbolAddress((void**)&QS, g_QS);
    cudaGetSymbolAddress((void**)&KS, g_KS);

    cudaFuncSetAttribute(dist_mma_kernel, cudaFuncAttributeMaxDynamicSharedMemorySize,
                         MSM_TOTAL);
    cudaFuncSetAttribute(conv_mma_kernel<128>, cudaFuncAttributeMaxDynamicSharedMemorySize,
                         3 * 32768);
    cudaFuncSetAttribute(conv_mma_kernel<64>, cudaFuncAttributeMaxDynamicSharedMemorySize,
                         3 * 24576);

    prep_kernel<<<(C2 * 288 + C3 * 576 + 255) / 256, 256>>>(w2, w3, Wh2, Wm2, Wh3, Wm3);
    conv1_kernel<<<dim3(NPIX / 256, 8), 256>>>(x1, x2, w1, b1, T1);
    im2col_kernel<<<dim3(288, 8, 8), 256>>>(T1, C1, ICh, ICm);
    conv_mma_kernel<64><<<dim3(32, 1, 8), 256, 3 * 24576>>>(
        Wh2, Wm2, ICh, ICm, 288, b2, T2, (long)C2 * NPIX, T2 + (long)NB * C2 * NPIX,
        (long)C2 * NPIX);
    im2col_kernel<<<dim3(576, 8, 8), 256>>>(T2, C2, ICh, ICm);
    conv_mma_kernel<128><<<dim3(32, 2, 8), 256, 3 * 32768>>>(
        Wh3, Wm3, ICh, ICm, 576, b3, out, (long)512 * NPIX, F2, (long)C3 * NPIX);
    split_kernel<<<dim3(NPIX / 64, 2, NB), 256>>>(out, F2, QS, KS, B2N, AMIN);
    dist_mma_kernel<<<dim3(32, 16, NB), 512, MSM_TOTAL>>>(QS, KS, B2N, AMIN);
    gather_kernel<<<(int)(((long)NB * C3 * NPIX + 255) / 256), 256>>>(F2, AMIN, out);
}

// round 17
// speedup vs baseline: 1.0681x; 1.0681x over previous
#include <cuda_runtime.h>
#include <cuda_fp16.h>
#include <cstdint>

#define HH 64
#define WW 64
#define NPIX 4096
#define NB 4
#define C1 32
#define C2 64
#define C3 256

typedef unsigned long long ull;

__device__ __forceinline__ uint32_t smem_u32(const void* p) {
    uint32_t a;
    asm("{ .reg .u64 t; cvta.to.shared.u64 t, %1; cvt.u32.u64 %0, t; }" : "=r"(a) : "l"(p));
    return a;
}
#define CP_ASYNC16(dst, src) \
    asm volatile("cp.async.cg.shared.global [%0], [%1], 16;" :: "r"(dst), "l"(src) : "memory")
#define CP_COMMIT() asm volatile("cp.async.commit_group;" ::: "memory")
#define CP_WAIT1() asm volatile("cp.async.wait_group 1;" ::: "memory")
#define CP_WAIT0() asm volatile("cp.async.wait_group 0;" ::: "memory")
#define LDSM_X4(r0, r1, r2, r3, a) \
    asm volatile("ldmatrix.sync.aligned.m8n8.x4.shared.b16 {%0,%1,%2,%3}, [%4];" \
        : "=r"(r0), "=r"(r1), "=r"(r2), "=r"(r3) : "r"(a))
#define LDSM_X2(r0, r1, a) \
    asm volatile("ldmatrix.sync.aligned.m8n8.x2.shared.b16 {%0,%1}, [%2];" \
        : "=r"(r0), "=r"(r1) : "r"(a))
#define LDSM_X2T(r0, r1, a) \
    asm volatile("ldmatrix.sync.aligned.m8n8.x2.trans.shared.b16 {%0,%1}, [%2];" \
        : "=r"(r0), "=r"(r1) : "r"(a))
#define MMA_F16(d, a, bf) \
    asm volatile( \
        "mma.sync.aligned.m16n8k16.row.col.f32.f16.f16.f32 " \
        "{%0,%1,%2,%3}, {%4,%5,%6,%7}, {%8,%9}, {%0,%1,%2,%3};" \
        : "+f"((d)[0]), "+f"((d)[1]), "+f"((d)[2]), "+f"((d)[3]) \
        : "r"((a)[0]), "r"((a)[1]), "r"((a)[2]), "r"((a)[3]), "r"((bf)[0]), "r"((bf)[1]))

__device__ __forceinline__ uint32_t fkey(float f) {
    uint32_t b = __float_as_uint(f);
    return (b & 0x80000000u) ? ~b : (b | 0x80000000u);
}

// ---------------- static device scratch ----------------
__device__ float g_T1[2 * NB * C1 * NPIX];
__device__ float g_T2[2 * NB * C2 * NPIX];
__device__ __align__(16) __half g_ICh[(long)2 * NB * 576 * NPIX];
__device__ __align__(16) __half g_ICm[(long)2 * NB * 576 * NPIX];
__device__ float g_F2[NB * C3 * NPIX];
__device__ float g_B2N[NB * NPIX];
__device__ ull g_AMIN[NB * NPIX];
__device__ __align__(16) __half g_Wh2[C2 * 288];
__device__ __align__(16) __half g_Wm2[C2 * 288];
__device__ __align__(16) __half g_Wh3[C3 * 576];
__device__ __align__(16) __half g_Wm3[C3 * 576];
__device__ __align__(16) __half g_QS[(long)NB * NPIX * 512];
__device__ __align__(16) __half g_KS[(long)NB * NPIX * 512];

// ---------------- prep: split weights to fp16 h/m ----------------
__global__ void prep_kernel(const float* __restrict__ w2, const float* __restrict__ w3,
                            __half* __restrict__ Wh2, __half* __restrict__ Wm2,
                            __half* __restrict__ Wh3, __half* __restrict__ Wm3) {
    int t = blockIdx.x * blockDim.x + threadIdx.x;
    if (t < C2 * 288) {
        float x = w2[t];
        __half h = __float2half_rn(x);
        Wh2[t] = h;
        Wm2[t] = __float2half_rn(x - __half2float(h));
    } else {
        int u = t - C2 * 288;
        if (u < C3 * 576) {
            float x = w3[u];
            __half h = __float2half_rn(x);
            Wh3[u] = h;
            Wm3[u] = __float2half_rn(x - __half2float(h));
        }
    }
}

// ---------------- conv1 (fp32 direct) ----------------
__global__ void conv1_kernel(const float* __restrict__ x1, const float* __restrict__ x2,
                             const float* __restrict__ w, const float* __restrict__ bias,
                             float* __restrict__ out) {
    int p = blockIdx.x * blockDim.x + threadIdx.x;
    int z = blockIdx.y;
    if (p >= NPIX) return;
    const float* x = (z >> 2) ? x2 : x1;
    int b = z & 3;
    int y = p >> 6, xx = p & 63;
    const float* xb = x + (long)b * NPIX;
    float in[9];
#pragma unroll
    for (int ky = 0; ky < 3; ky++)
#pragma unroll
        for (int kx = 0; kx < 3; kx++) {
            int yy = y + ky - 1, xc = xx + kx - 1;
            in[ky * 3 + kx] =
                ((unsigned)yy < (unsigned)HH && (unsigned)xc < (unsigned)WW) ? xb[yy * WW + xc] : 0.f;
        }
#pragma unroll 4
    for (int co = 0; co < C1; co++) {
        float acc = bias[co];
#pragma unroll
        for (int t = 0; t < 9; t++) acc += w[co * 9 + t] * in[t];
        out[((long)z * C1 + co) * NPIX + p] = acc;
    }
}

// ---------------- im2col with fp16 h/m split ----------------
__global__ void im2col_kernel(const float* __restrict__ in, int CI,
                              __half* __restrict__ oh, __half* __restrict__ om) {
    int gk = blockIdx.x;
    int z = blockIdx.y;
    int n = ((blockIdx.z << 8) + threadIdx.x) << 1;
    int K = CI * 9;
    int ci = gk / 9;
    int tap = gk - ci * 9;
    int ky = tap / 3 - 1, kx = tap - (tap / 3) * 3 - 1;
    int y = (n >> 6) + ky;
    int x = (n & 63) + kx;
    const float* row = in + ((long)(z * CI + ci) << 12) + (y << 6);
    float v0 = 0.f, v1 = 0.f;
    if ((unsigned)y < 64u) {
        if ((unsigned)x < 64u) v0 = row[x];
        if ((unsigned)(x + 1) < 64u) v1 = row[x + 1];
    }
    __half h0 = __float2half_rn(v0), h1 = __float2half_rn(v1);
    long o = ((long)(z * K + gk) << 12) + n;
    *(__half2*)&oh[o] = __halves2half2(h0, h1);
    *(__half2*)&om[o] = __halves2half2(__float2half_rn(v0 - __half2float(h0)),
                                       __float2half_rn(v1 - __half2float(h1)));
}

// ---------------- conv via mma.sync fp16 3-product (round-15 proven) ----------------
template <int MROWS>
__global__ void __launch_bounds__(256, 2)
conv_mma_kernel(const __half* __restrict__ Wh, const __half* __restrict__ Wm,
                const __half* __restrict__ Bh, const __half* __restrict__ Bm, int K,
                const float* __restrict__ bias,
                float* __restrict__ outA, long sA, float* __restrict__ outB, long sB) {
    extern __shared__ __align__(16) char csm[];
    const int AG = MROWS * 4;
    const int STB = (2 * AG + 1024) * 16;
    const int ABYT = 2 * AG * 16;
    const int TMT = MROWS / 32;
    uint32_t sb = smem_u32(csm);
    int z = blockIdx.z, sel = z >> 2, bb = z & 3;
    float* out = sel ? outB : outA;
    long os = sel ? sB : sA;
    int m0 = blockIdx.y * MROWS;
    int n0 = blockIdx.x * 128;
    int tid = threadIdx.x;
    int lane = tid & 31, wid = tid >> 5;
    int wm = wid & 1, wn = wid >> 1;
    long zK = (long)z * K;

    float acc[TMT][4][4];
#pragma unroll
    for (int mt = 0; mt < TMT; mt++)
#pragma unroll
        for (int nt = 0; nt < 4; nt++)
#pragma unroll
            for (int q = 0; q < 4; q++) acc[mt][nt][q] = 0.f;

    auto issue = [&](int c, int st) {
        int kb = c * 32;
        uint32_t da = sb + (uint32_t)st * STB;
        uint32_t db = da + ABYT;
#pragma unroll
        for (int it = 0; it < 2 * AG / 256; it++) {
            int e = tid + it * 256;
            int seg = e / AG;
            int r = (e % AG) >> 2;
            int k8 = e & 3;
            uint32_t g = (uint32_t)(seg * AG + r * 4 + (k8 ^ ((r >> 1) & 3))) << 4;
            const __half* src = (seg ? Wm : Wh) + (long)(m0 + r) * K + kb + k8 * 8;
            CP_ASYNC16(da + g, src);
        }
#pragma unroll
        for (int it = 0; it < 4; it++) {
            int e = tid + it * 256;
            int seg = e >> 9;
            int k = (e >> 4) & 31;
            int ng = e & 15;
            uint32_t g = (uint32_t)(seg * 512 + k * 16 + (ng ^ (k & 15))) << 4;
            const __half* src = (seg ? Bm : Bh) + ((zK + kb + k) << 12) + n0 + ng * 8;
            CP_ASYNC16(db + g, src);
        }
        CP_COMMIT();
    };

    int NCH = K / 32;
    issue(0, 0);
    issue(1, 1);

    for (int c = 0; c < NCH; c++) {
        int st = c % 3;
        if (c + 1 < NCH) CP_WAIT1(); else CP_WAIT0();
        __syncthreads();
        if (c + 2 < NCH) issue(c + 2, (c + 2) % 3);
        uint32_t Ab = sb + (uint32_t)st * STB;
        uint32_t Bb = Ab + ABYT;
#pragma unroll
        for (int ks = 0; ks < 2; ks++) {
            uint32_t bf[2][4][2];
#pragma unroll
            for (int sk = 0; sk < 2; sk++)
#pragma unroll
                for (int nt = 0; nt < 4; nt++) {
                    int k = ks * 16 + (lane & 15);
                    int ng = wn * 4 + nt;
                    uint32_t g = (uint32_t)(sk * 512 + k * 16 + (ng ^ (k & 15))) << 4;
                    LDSM_X2T(bf[sk][nt][0], bf[sk][nt][1], Bb + g);
                }
#pragma unroll
            for (int sq = 0; sq < 2; sq++) {
                uint32_t af[TMT][4];
#pragma unroll
                for (int mt = 0; mt < TMT; mt++) {
                    int row = wm * (MROWS / 2) + mt * 16 + (lane & 15);
                    int k8 = ks * 2 + (lane >> 4);
                    uint32_t g = (uint32_t)(sq * AG + row * 4 + (k8 ^ ((row >> 1) & 3))) << 4;
                    LDSM_X4(af[mt][0], af[mt][1], af[mt][2], af[mt][3], Ab + g);
                }
                int nsk = 2 - sq;
#pragma unroll
                for (int sk = 0; sk < 2; sk++) {
                    if (sk >= nsk) break;
#pragma unroll
                    for (int mt = 0; mt < TMT; mt++)
#pragma unroll
                        for (int nt = 0; nt < 4; nt++) MMA_F16(acc[mt][nt], af[mt], bf[sk][nt]);
                }
            }
        }
    }
#pragma unroll
    for (int mt = 0; mt < TMT; mt++) {
        int co0 = m0 + wm * (MROWS / 2) + mt * 16 + (lane >> 2);
        int co1 = co0 + 8;
        float b0 = bias[co0], b1 = bias[co1];
        long base0 = (long)bb * os + ((long)co0 << 12) + n0;
        long base1 = (long)bb * os + ((long)co1 << 12) + n0;
#pragma unroll
        for (int nt = 0; nt < 4; nt++) {
            int nn = wn * 32 + nt * 8 + (lane & 3) * 2;
            float2 o0, o1;
            o0.x = acc[mt][nt][0] + b0;
            o0.y = acc[mt][nt][1] + b0;
            o1.x = acc[mt][nt][2] + b1;
            o1.y = acc[mt][nt][3] + b1;
            *(float2*)&out[base0 + nn] = o0;
            *(float2*)&out[base1 + nn] = o1;
        }
    }
}

// ---------------- split to fp16 h/m stacks + key norms + AMIN init ----------------
__global__ void split_kernel(const float* __restrict__ f1out, const float* __restrict__ f2,
                             __half* __restrict__ QS, __half* __restrict__ KS,
                             float* __restrict__ b2n, ull* __restrict__ amin) {
    __shared__ __half sh[2][64][64];
    __shared__ float snorm[256];
    int n0 = blockIdx.x * 64;
    int src = blockIdx.y;
    int b = blockIdx.z;
    const float* f = src ? (f2 + (long)b * C3 * NPIX) : (f1out + (long)b * 512 * NPIX);
    __half* dst = (src ? KS : QS) + (long)b * NPIX * 512;
    int tid = threadIdx.x;
    int nl = tid & 63, cq = tid >> 6;
    if (src == 0 && tid < 64) amin[b * NPIX + n0 + tid] = ~0ull;
    float nacc = 0.f;
    for (int cc = 0; cc < 4; cc++) {
        int cbase = cc * 64;
#pragma unroll
        for (int r = 0; r < 16; r++) {
            int cl = cq + r * 4;
            float x = f[(long)(cbase + cl) * NPIX + n0 + nl];
            __half h = __float2half_rn(x);
            sh[0][cl][nl] = h;
            sh[1][cl][nl] = __float2half_rn(x - __half2float(h));
            nacc += x * x;
        }
        __syncthreads();
        int nl2 = tid >> 2;
        int cg = (tid & 3) * 16;
#pragma unroll
        for (int s = 0; s < 2; s++) {
            __half* drow = dst + (long)(n0 + nl2) * 512 + s * 256 + cbase + cg;
#pragma unroll
            for (int j = 0; j < 16; j++) drow[j] = sh[s][cg + j][nl2];
        }
        __syncthreads();
    }
    if (src == 1) {
        snorm[tid] = nacc;
        __syncthreads();
        if (tid < 64)
            b2n[(long)b * NPIX + n0 + tid] =
                snorm[tid] + snorm[tid + 64] + snorm[tid + 128] + snorm[tid + 192];
    }
}

// ---------------- dist GEMM + argmin: 128x128, fp16 3-product, 3-stage (round-15 proven)
//                  + fused atomicMin merge ----------------
#define MST 32768
#define MSM_TOTAL (3 * MST)

__global__ void __launch_bounds__(256, 2)
dist_mma_kernel(const __half* __restrict__ QS, const __half* __restrict__ KS,
                const float* __restrict__ b2n, ull* __restrict__ amin) {
    extern __shared__ __align__(16) char dsm[];
    uint32_t sb = smem_u32(dsm);
    int b = blockIdx.z;
    int jq = blockIdx.y;
    int j0 = jq * 128;
    int i0 = blockIdx.x * 128;
    int tid = threadIdx.x;
    int lane = tid & 31, wid = tid >> 5;
    int wm = wid & 1, wn = wid >> 1;

    const __half* Qb = QS + (long)(b * NPIX + i0) * 512;
    const __half* Kb = KS + (long)(b * NPIX + j0) * 512;
    const float* bn = b2n + (long)b * NPIX;

    float acc[4][4][4];
#pragma unroll
    for (int mt = 0; mt < 4; mt++)
#pragma unroll
        for (int nt = 0; nt < 4; nt++)
#pragma unroll
            for (int q = 0; q < 4; q++) acc[mt][nt][q] = 0.f;

    auto issue = [&](int c, int st) {
        uint32_t dq = sb + (uint32_t)st * MST;
        uint32_t dk = dq + 16384;
        int kb = c * 32;
#pragma unroll
        for (int it = 0; it < 4; it++) {
            int e = tid + it * 256;
            int s = e >> 9;
            int row = (e >> 2) & 127;
            int k8 = e & 3;
            uint32_t g = (uint32_t)((s << 9) + row * 4 + (k8 ^ ((row >> 1) & 3))) << 4;
            const __half* sq = Qb + (long)row * 512 + s * 256 + kb + k8 * 8;
            const __half* sk = Kb + (long)row * 512 + s * 256 + kb + k8 * 8;
            CP_ASYNC16(dq + g, sq);
            CP_ASYNC16(dk + g, sk);
        }
        CP_COMMIT();
    };

    const int NCH = 8;
    issue(0, 0);
    issue(1, 1);

    for (int c = 0; c < NCH; c++) {
        int st = c % 3;
        if (c + 1 < NCH) CP_WAIT1(); else CP_WAIT0();
        __syncthreads();
        if (c + 2 < NCH) issue(c + 2, (c + 2) % 3);
        uint32_t Ab = sb + (uint32_t)st * MST;
        uint32_t Bb = Ab + 16384;
#pragma unroll
        for (int ks = 0; ks < 2; ks++) {
            uint32_t bf[2][4][2];
#pragma unroll
            for (int sk = 0; sk < 2; sk++)
#pragma unroll
                for (int nt = 0; nt < 4; nt++) {
                    int rowb = wn * 32 + nt * 8 + (lane & 7);
                    int k8 = ks * 2 + ((lane >> 3) & 1);
                    uint32_t g = (uint32_t)((sk << 9) + rowb * 4 + (k8 ^ ((rowb >> 1) & 3))) << 4;
                    LDSM_X2(bf[sk][nt][0], bf[sk][nt][1], Bb + g);
                }
#pragma unroll
            for (int sq = 0; sq < 2; sq++) {
                uint32_t af[4][4];
#pragma unroll
                for (int mt = 0; mt < 4; mt++) {
                    int row = wm * 64 + mt * 16 + (lane & 15);
                    int k8 = ks * 2 + (lane >> 4);
                    uint32_t g = (uint32_t)((sq << 9) + row * 4 + (k8 ^ ((row >> 1) & 3))) << 4;
                    LDSM_X4(af[mt][0], af[mt][1], af[mt][2], af[mt][3], Ab + g);
                }
                int nsk = 2 - sq;
#pragma unroll
                for (int sk = 0; sk < 2; sk++) {
                    if (sk >= nsk) break;
#pragma unroll
                    for (int mt = 0; mt < 4; mt++)
#pragma unroll
                        for (int nt = 0; nt < 4; nt++) MMA_F16(acc[mt][nt], af[mt], bf[sk][nt]);
                }
            }
        }
    }

    float bnv[4][2];
#pragma unroll
    for (int nt = 0; nt < 4; nt++) {
        int jj = j0 + wn * 32 + nt * 8 + (lane & 3) * 2;
        bnv[nt][0] = __ldg(&bn[jj]);
        bnv[nt][1] = __ldg(&bn[jj + 1]);
    }
    float bvA[4], bvB[4];
    int biA[4], biB[4];
#pragma unroll
    for (int mt = 0; mt < 4; mt++) {
        bvA[mt] = 3.4e38f; biA[mt] = 0;
        bvB[mt] = 3.4e38f; biB[mt] = 0;
#pragma unroll
        for (int nt = 0; nt < 4; nt++)
#pragma unroll
            for (int p = 0; p < 2; p++) {
                int j = j0 + wn * 32 + nt * 8 + (lane & 3) * 2 + p;
                float dA = bnv[nt][p] - 2.f * acc[mt][nt][p];
                if (dA < bvA[mt]) { bvA[mt] = dA; biA[mt] = j; }
                float dB = bnv[nt][p] - 2.f * acc[mt][nt][2 + p];
                if (dB < bvB[mt]) { bvB[mt] = dB; biB[mt] = j; }
            }
#pragma unroll
        for (int m = 1; m <= 2; m <<= 1) {
            float ov = __shfl_xor_sync(0xffffffffu, bvA[mt], m);
            int oi = __shfl_xor_sync(0xffffffffu, biA[mt], m);
            if (ov < bvA[mt] || (ov == bvA[mt] && oi < biA[mt])) { bvA[mt] = ov; biA[mt] = oi; }
            ov = __shfl_xor_sync(0xffffffffu, bvB[mt], m);
            oi = __shfl_xor_sync(0xffffffffu, biB[mt], m);
            if (ov < bvB[mt] || (ov == bvB[mt] && oi < biB[mt])) { bvB[mt] = ov; biB[mt] = oi; }
        }
    }
    __syncthreads();
    float* rv = (float*)dsm;
    int* ri = (int*)(dsm + 2048);
    if ((lane & 3) == 0) {
#pragma unroll
        for (int mt = 0; mt < 4; mt++) {
            int r = wm * 64 + mt * 16 + (lane >> 2);
            rv[wn * 128 + r] = bvA[mt];
            ri[wn * 128 + r] = biA[mt];
            rv[wn * 128 + r + 8] = bvB[mt];
            ri[wn * 128 + r + 8] = biB[mt];
        }
    }
    __syncthreads();
    if (tid < 128) {
        float bv = rv[tid];
        int bi = ri[tid];
#pragma unroll
        for (int w = 1; w < 4; w++) {
            float v = rv[w * 128 + tid];
            int ii = ri[w * 128 + tid];
            if (v < bv || (v == bv && ii < bi)) { bv = v; bi = ii; }
        }
        ull key = ((ull)fkey(bv) << 32) | (uint32_t)bi;
        atomicMin(&amin[b * NPIX + i0 + tid], key);
    }
}

// ---------------- gather (reads atomic argmin result) ----------------
__global__ void gather_kernel(const float* __restrict__ f2, const ull* __restrict__ amin,
                              float* __restrict__ out) {
    long t = (long)blockIdx.x * blockDim.x + threadIdx.x;
    if (t >= (long)NB * C3 * NPIX) return;
    int j = (int)(t & (NPIX - 1));
    int c = (int)((t >> 12) & 255);
    int b = (int)(t >> 20);
    int id = (int)(amin[b * NPIX + j] & 0xFFFFFFFFull);
    out[((long)b * 512 + 256 + c) * NPIX + j] = f2[((long)b * C3 + c) * NPIX + id];
}

// ---------------- launch ----------------
extern "C" void kernel_launch(void* const* d_in, const int* in_sizes, int n_in,
                              void* d_out, int out_size) {
    const float* x1 = (const float*)d_in[0];
    const float* x2 = (const float*)d_in[1];
    const float* w1 = (const float*)d_in[2];
    const float* b1 = (const float*)d_in[3];
    const float* w2 = (const float*)d_in[4];
    const float* b2 = (const float*)d_in[5];
    const float* w3 = (const float*)d_in[6];
    const float* b3 = (const float*)d_in[7];
    float* out = (float*)d_out;

    float *T1, *T2, *F2, *B2N;
    ull* AMIN;
    __half *ICh, *ICm, *Wh2, *Wm2, *Wh3, *Wm3, *QS, *KS;
    cudaGetSymbolAddress((void**)&T1, g_T1);
    cudaGetSymbolAddress((void**)&T2, g_T2);
    cudaGetSymbolAddress((void**)&ICh, g_ICh);
    cudaGetSymbolAddress((void**)&ICm, g_ICm);
    cudaGetSymbolAddress((void**)&F2, g_F2);
    cudaGetSymbolAddress((void**)&B2N, g_B2N);
    cudaGetSymbolAddress((void**)&AMIN, g_AMIN);
    cudaGetSymbolAddress((void**)&Wh2, g_Wh2);
    cudaGetSymbolAddress((void**)&Wm2, g_Wm2);
    cudaGetSymbolAddress((void**)&Wh3, g_Wh3);
    cudaGetSymbolAddress((void**)&Wm3, g_Wm3);
    cudaGetSymbolAddress((void**)&QS, g_QS);
    cudaGetSymbolAddress((void**)&KS, g_KS);

    cudaFuncSetAttribute(dist_mma_kernel, cudaFuncAttributeMaxDynamicSharedMemorySize,
                         MSM_TOTAL);
    cudaFuncSetAttribute(conv_mma_kernel<128>, cudaFuncAttributeMaxDynamicSharedMemorySize,
                         3 * 32768);
    cudaFuncSetAttribute(conv_mma_kernel<64>, cudaFuncAttributeMaxDynamicSharedMemorySize,
                         3 * 24576);

    prep_kernel<<<(C2 * 288 + C3 * 576 + 255) / 256, 256>>>(w2, w3, Wh2, Wm2, Wh3, Wm3);
    conv1_kernel<<<dim3(NPIX / 256, 8), 256>>>(x1, x2, w1, b1, T1);
    im2col_kernel<<<dim3(288, 8, 8), 256>>>(T1, C1, ICh, ICm);
    conv_mma_kernel<64><<<dim3(32, 1, 8), 256, 3 * 24576>>>(
        Wh2, Wm2, ICh, ICm, 288, b2, T2, (long)C2 * NPIX, T2 + (long)NB * C2 * NPIX,
        (long)C2 * NPIX);
    im2col_kernel<<<dim3(576, 8, 8), 256>>>(T2, C2, ICh, ICm);
    conv_mma_kernel<128><<<dim3(32, 2, 8), 256, 3 * 32768>>>(
        Wh3, Wm3, ICh, ICm, 576, b3, out, (long)512 * NPIX, F2, (long)C3 * NPIX);
    split_kernel<<<dim3(NPIX / 64, 2, NB), 256>>>(out, F2, QS, KS, B2N, AMIN);
    dist_mma_kernel<<<dim3(32, 32, NB), 256, MSM_TOTAL>>>(QS, KS, B2N, AMIN);
    gather_kernel<<<(int)(((long)NB * C3 * NPIX + 255) / 256), 256>>>(F2, AMIN, out);
}